// round 5
// baseline (speedup 1.0000x reference)
#include <cuda_runtime.h>
#include <cstdint>

#define BATCH 8
#define NSEQ  1024
#define DIM   512
#define NH    8
#define DH    64
#define BH    64
#define SCALE 0.044194173824159216f   // 512^-0.5

// ---------------- scratch (device globals: alloc-guard safe) ----------------
__device__ float g_q1[BH*NSEQ*DH];
__device__ float g_k1[BH*NSEQ*DH];
__device__ float g_v1[BH*NSEQ*DH];     // TRANSPOSED: [bh][d][n]
__device__ float g_o1[BATCH*NSEQ*DIM];
__device__ float g_q2[BH*NSEQ*DH];
__device__ float g_k2[BH*NSEQ*DH];
__device__ float g_v2[BH*NSEQ*DH];     // TRANSPOSED: [bh][d][n]
__device__ float g_att[BATCH*NSEQ*DIM];
__device__ float g_xc[BATCH*NSEQ*DIM]; // tf32-rounded x
__device__ float g_w1[3*DIM*DIM];      // tf32-rounded W^T: [n][k]
__device__ float g_w2[3*DIM*DIM];
__device__ float g_wn[DIM*DIM];

// ---------------- helpers ----------------
__device__ __forceinline__ uint32_t f2tf(float x) {
    uint32_t r;
    asm("cvt.rna.tf32.f32 %0, %1;" : "=r"(r) : "f"(x));
    return r;
}
__device__ __forceinline__ float u2f(uint32_t u) { return __uint_as_float(u); }

__device__ __forceinline__ void mma8(float* c, const uint32_t* a, const uint32_t* b) {
    asm volatile(
        "mma.sync.aligned.m16n8k8.row.col.f32.tf32.tf32.f32 "
        "{%0,%1,%2,%3}, {%4,%5,%6,%7}, {%8,%9}, {%0,%1,%2,%3};\n"
        : "+f"(c[0]), "+f"(c[1]), "+f"(c[2]), "+f"(c[3])
        : "r"(a[0]), "r"(a[1]), "r"(a[2]), "r"(a[3]), "r"(b[0]), "r"(b[1]));
}
__device__ __forceinline__ void ldsm4(uint32_t& r0, uint32_t& r1, uint32_t& r2, uint32_t& r3,
                                      uint32_t addr) {
    asm volatile("ldmatrix.sync.aligned.m8n8.x4.shared.b16 {%0,%1,%2,%3}, [%4];"
        : "=r"(r0), "=r"(r1), "=r"(r2), "=r"(r3) : "r"(addr));
}
__device__ __forceinline__ void cpa16(uint32_t dst, const void* src) {
    asm volatile("cp.async.cg.shared.global [%0], [%1], 16;" :: "r"(dst), "l"(src));
}
#define CP_COMMIT()  asm volatile("cp.async.commit_group;")
#define CP_WAIT(n)   asm volatile("cp.async.wait_group " #n ";")

// ---------------- pre-pass: tf32 round (x) ----------------
__global__ void cvt_tf32(const float4* __restrict__ src, float4* __restrict__ dst, int n4) {
    int i = blockIdx.x * 256 + threadIdx.x;
    if (i < n4) {
        float4 v = src[i];
        dst[i] = make_float4(u2f(f2tf(v.x)), u2f(f2tf(v.y)), u2f(f2tf(v.z)), u2f(f2tf(v.w)));
    }
}

// ---------------- pre-pass: tf32 round + transpose (weights) ----------------
// W[K][N] -> Wt[N][K]
__global__ __launch_bounds__(256) void transpose_w(
    const float* __restrict__ W, float* __restrict__ Wt, int Kd, int Nd)
{
    __shared__ float tile[32][33];
    const int tx = threadIdx.x, ty = threadIdx.y;     // (32, 8)
    const int n0 = blockIdx.x * 32, k0 = blockIdx.y * 32;
    #pragma unroll
    for (int i = 0; i < 4; i++)
        tile[ty + 8*i][tx] = u2f(f2tf(W[(k0 + ty + 8*i)*Nd + n0 + tx]));
    __syncthreads();
    #pragma unroll
    for (int i = 0; i < 4; i++)
        Wt[(n0 + ty + 8*i)*Kd + k0 + tx] = tile[tx][ty + 8*i];
}

// ---------------- GEMM: C[M,Nc] = A[M,512] @ Wt^T + bias ----------------
// A tf32-in-f32 [M][512]; Wt tf32-in-f32 [Nc][512]. Block 128x128, 8 warps
// (warp 32x64), k-chunk 32, cp.async double-buffered, all fragments ldmatrix.
// smem per buf: As[128][36] (4608 w) + Bs[128][36] (4608 w) = 9216 w = 36864 B.
template<int QKV>
__global__ __launch_bounds__(256) void gemm_tf32(
    const float* __restrict__ A, const float* __restrict__ Wt,
    const float* __restrict__ bias, float* __restrict__ C,
    float* __restrict__ Qo, float* __restrict__ Ko, float* __restrict__ Vo,
    float qscale)
{
    extern __shared__ uint32_t sm[];
    const int tid = threadIdx.x, warp = tid >> 5, lane = tid & 31;
    const int wm = warp & 3, wn = warp >> 2, lr = lane >> 2, lc = lane & 3;
    const int row0 = blockIdx.y * 128, col0 = blockIdx.x * 128;
    const uint32_t smb = (uint32_t)__cvta_generic_to_shared(sm);

    float acc[2][8][4] = {};

    // prologue: k-tile 0 (buf 0)
    #pragma unroll
    for (int p = 0; p < 4; p++) {
        const int s = tid + 256*p;
        const int r = s >> 3, c4 = (s & 7) * 4;
        cpa16(smb + (r*36 + c4)*4,        &A [(row0 + r)*DIM + c4]);
        cpa16(smb + (4608 + r*36 + c4)*4, &Wt[(col0 + r)*DIM + c4]);
    }
    CP_COMMIT();

    // ldmatrix bases (bytes); As row stride 144 B, Bs at +18432 B
    const uint32_t abase = smb + (wm*32 + ((lane>>3)&1)*8 + (lane&7))*144 + (lane>>4)*16;
    const uint32_t bbase = smb + 18432 + (wn*64 + (lane&7))*144 + (lane>>3)*16;

    for (int i = 0; i < 16; i++) {
        const int bu = i & 1;
        if (i < 15) {
            const int nb = bu ^ 1, kt = (i+1)*32;
            #pragma unroll
            for (int p = 0; p < 4; p++) {
                const int s = tid + 256*p;
                const int r = s >> 3, c4 = (s & 7) * 4;
                cpa16(smb + (nb*9216 + r*36 + c4)*4,        &A [(row0 + r)*DIM + kt + c4]);
                cpa16(smb + (nb*9216 + 4608 + r*36 + c4)*4, &Wt[(col0 + r)*DIM + kt + c4]);
            }
            CP_COMMIT();
            CP_WAIT(1);
        } else {
            CP_WAIT(0);
        }
        __syncthreads();

        // A fragments: 8 ldmatrix (mt x ksg)
        uint32_t af[2][4][4];
        #pragma unroll
        for (int mt = 0; mt < 2; mt++)
            #pragma unroll
            for (int ksg = 0; ksg < 4; ksg++)
                ldsm4(af[mt][ksg][0], af[mt][ksg][1], af[mt][ksg][2], af[mt][ksg][3],
                      abase + bu*36864 + mt*2304 + ksg*32);

        // B fragments + mma: 16 ldmatrix, 64 mma
        #pragma unroll
        for (int nt = 0; nt < 8; nt++) {
            #pragma unroll
            for (int kg2 = 0; kg2 < 2; kg2++) {
                uint32_t b0, b1, b2, b3;
                ldsm4(b0, b1, b2, b3, bbase + bu*36864 + nt*1152 + kg2*64);
                uint32_t bfa[2] = {b0, b1}, bfb[2] = {b2, b3};
                mma8(acc[0][nt], af[0][2*kg2],   bfa);
                mma8(acc[1][nt], af[1][2*kg2],   bfa);
                mma8(acc[0][nt], af[0][2*kg2+1], bfb);
                mma8(acc[1][nt], af[1][2*kg2+1], bfb);
            }
        }
        __syncthreads();
    }

    // epilogue
    #pragma unroll
    for (int mt = 0; mt < 2; mt++) {
        const int rbase = row0 + wm*32 + mt*16 + lr;
        #pragma unroll
        for (int nt = 0; nt < 8; nt++) {
            const int cc = col0 + wn*64 + nt*8 + 2*lc;
            const float b0 = bias[cc], b1 = bias[cc+1];
            #pragma unroll
            for (int h2 = 0; h2 < 2; h2++) {
                const int r = rbase + h2*8;
                float v0 = acc[mt][nt][h2*2]   + b0;
                float v1 = acc[mt][nt][h2*2+1] + b1;
                if (QKV) {
                    const int part = cc >> 9;
                    const int hh   = (cc >> 6) & 7;
                    const int dd   = cc & 63;
                    const int bb   = r >> 10;
                    const int nn   = r & 1023;
                    const int bhh  = bb*NH + hh;
                    if (part == 0) { v0 *= qscale; v1 *= qscale; }
                    v0 = u2f(f2tf(v0)); v1 = u2f(f2tf(v1));
                    if (part == 2) {   // V transposed: [bh][d][n]
                        Vo[(bhh*DH + dd)*NSEQ + nn]     = v0;
                        Vo[(bhh*DH + dd + 1)*NSEQ + nn] = v1;
                    } else {
                        float* dst = (part == 0) ? Qo : Ko;
                        *(float2*)&dst[(bhh*NSEQ + nn)*DH + dd] = make_float2(v0, v1);
                    }
                } else {
                    *(float2*)&C[r*DIM + cc] = make_float2(v0, v1);
                }
            }
        }
    }
}

// ---------------- flash attention (tf32 mma, all-ldmatrix) ----------------
// Block: 64 queries, 4 warps, 64-key tiles, double-buffered K + Vt.
// K [bh][n][d]; V TRANSPOSED [bh][d][n]; Q pre-scaled for stage 2.
// smem per buf (8704 w = 34816 B): K[64][68] then Vt[64][68].
template<bool STAGE1>
__global__ __launch_bounds__(128, 3) void attn_tf32(
    const float* __restrict__ Q, const float* __restrict__ K,
    const float* __restrict__ V, const float* __restrict__ mask,
    float* __restrict__ out)
{
    extern __shared__ uint32_t sm[];
    const int tid = threadIdx.x, warp = tid >> 5, lane = tid & 31;
    const int lr = lane >> 2, lc = lane & 3;
    const int bh = blockIdx.x, qt = blockIdx.y;
    const int b = bh >> 3, h = bh & 7;
    const uint32_t smb = (uint32_t)__cvta_generic_to_shared(sm);

    const float4* Qsrc  = (const float4*)(Q + (bh*NSEQ + qt*64)*DH);
    const float4* Ksrc  = (const float4*)(K + bh*NSEQ*DH);
    const float4* Vtsrc = (const float4*)(V + bh*DH*NSEQ);

    // prologue: Q -> K region of buf1; tile 0 -> buf0
    #pragma unroll
    for (int s5 = 0; s5 < 8; s5++) {
        const int idx = tid + 128*s5;
        const int row = idx >> 4, c16 = idx & 15;
        cpa16(smb + (8704 + row*68 + c16*4)*4, Qsrc + idx);
    }
    CP_COMMIT();
    #pragma unroll
    for (int s5 = 0; s5 < 8; s5++) {
        const int idx = tid + 128*s5;
        const int row = idx >> 4, c16 = idx & 15;
        cpa16(smb + (row*68 + c16*4)*4, Ksrc + row*16 + c16);
        cpa16(smb + (4352 + row*68 + c16*4)*4, Vtsrc + row*256 + c16);
    }
    CP_COMMIT();
    CP_WAIT(0);
    __syncthreads();

    // Q fragments via ldmatrix
    uint32_t qf[8][4];
    {
        const uint32_t qb = smb + 34816
            + (warp*16 + ((lane >> 3) & 1)*8 + (lane & 7))*272 + (lane >> 4)*16;
        #pragma unroll
        for (int ks = 0; ks < 8; ks++)
            ldsm4(qf[ks][0], qf[ks][1], qf[ks][2], qf[ks][3], qb + ks*32);
    }
    __syncthreads();   // Q region may now be overwritten by tile 1

    float o[8][4] = {};
    float mrow[2] = {-1e30f, -1e30f}, lrow[2] = {0.f, 0.f};

    const uint32_t foff = (lane & 7)*272 + (lane >> 3)*16;   // B-frag ldmatrix offset
    const unsigned p0l = (lane & 28) | (lc >> 1);
    const unsigned p1l = p0l | 2;

    for (int t = 0; t < 16; t++) {
        const int bu = t & 1;
        if (t < 15) {
            const int nb = bu ^ 1;
            #pragma unroll
            for (int s5 = 0; s5 < 8; s5++) {
                const int idx = tid + 128*s5;
                const int row = idx >> 4, c16 = idx & 15;
                cpa16(smb + (nb*8704 + row*68 + c16*4)*4,
                      Ksrc + ((t+1)*64 + row)*16 + c16);
                cpa16(smb + (nb*8704 + 4352 + row*68 + c16*4)*4,
                      Vtsrc + row*256 + (t+1)*16 + c16);
            }
            CP_COMMIT();
            CP_WAIT(1);
        } else {
            CP_WAIT(0);
        }
        __syncthreads();

        // ---- S = Q @ K^T ----
        float s[8][4];
        #pragma unroll
        for (int nt = 0; nt < 8; nt++)
            #pragma unroll
            for (int u = 0; u < 4; u++) s[nt][u] = 0.f;

        const uint32_t kb = smb + bu*34816 + foff;
        #pragma unroll
        for (int nt = 0; nt < 8; nt++) {
            #pragma unroll
            for (int kg = 0; kg < 4; kg++) {
                uint32_t b0, b1, b2, b3;
                ldsm4(b0, b1, b2, b3, kb + nt*2176 + kg*64);
                uint32_t bfa[2] = {b0, b1}, bfb[2] = {b2, b3};
                mma8(s[nt], qf[2*kg],   bfa);
                mma8(s[nt], qf[2*kg+1], bfb);
            }
        }

        // ---- elementwise ----
        if (STAGE1) {
            const int qrow0 = qt*64 + warp*16 + lr;
            #pragma unroll
            for (int nt = 0; nt < 8; nt++) {
                const int ccol = t*64 + nt*8 + 2*lc;
                float2 m0v = *(const float2*)(mask + qrow0*NSEQ + ccol);
                float2 m1v = *(const float2*)(mask + (qrow0+8)*NSEQ + ccol);
                s[nt][0] = 1.f / (1.f + __expf(-s[nt][0]*m0v.x));
                s[nt][1] = 1.f / (1.f + __expf(-s[nt][1]*m0v.y));
                s[nt][2] = 1.f / (1.f + __expf(-s[nt][2]*m1v.x));
                s[nt][3] = 1.f / (1.f + __expf(-s[nt][3]*m1v.y));
            }
        } else {
            #pragma unroll
            for (int h2 = 0; h2 < 2; h2++) {
                float tmax = -1e30f;
                #pragma unroll
                for (int nt = 0; nt < 8; nt++)
                    tmax = fmaxf(tmax, fmaxf(s[nt][h2*2], s[nt][h2*2+1]));
                tmax = fmaxf(tmax, __shfl_xor_sync(0xffffffffu, tmax, 1));
                tmax = fmaxf(tmax, __shfl_xor_sync(0xffffffffu, tmax, 2));
                const float mnew  = fmaxf(mrow[h2], tmax);
                const float alpha = __expf(mrow[h2] - mnew);
                mrow[h2] = mnew;
                float rsum = 0.f;
                #pragma unroll
                for (int nt = 0; nt < 8; nt++) {
                    const float p0 = __expf(s[nt][h2*2]   - mnew);
                    const float p1 = __expf(s[nt][h2*2+1] - mnew);
                    rsum += p0 + p1;
                    s[nt][h2*2]   = p0;
                    s[nt][h2*2+1] = p1;
                    o[nt][h2*2]   *= alpha;
                    o[nt][h2*2+1] *= alpha;
                }
                rsum += __shfl_xor_sync(0xffffffffu, rsum, 1);
                rsum += __shfl_xor_sync(0xffffffffu, rsum, 2);
                lrow[h2] = lrow[h2]*alpha + rsum;
            }
        }

        // ---- C-frag -> A-frag via shuffles ----
        uint32_t pa[8][4];
        #pragma unroll
        for (int k = 0; k < 8; k++) {
            const float e0 = __shfl_sync(0xffffffffu, s[k][0], p0l);
            const float e1 = __shfl_sync(0xffffffffu, s[k][1], p0l);
            const float e2 = __shfl_sync(0xffffffffu, s[k][2], p0l);
            const float e3 = __shfl_sync(0xffffffffu, s[k][3], p0l);
            const float f0 = __shfl_sync(0xffffffffu, s[k][0], p1l);
            const float f1 = __shfl_sync(0xffffffffu, s[k][1], p1l);
            const float g2 = __shfl_sync(0xffffffffu, s[k][2], p1l);
            const float g3 = __shfl_sync(0xffffffffu, s[k][3], p1l);
            const bool odd = lc & 1;
            pa[k][0] = f2tf(odd ? e1 : e0);
            pa[k][1] = f2tf(odd ? e3 : e2);
            pa[k][2] = f2tf(odd ? f1 : f0);
            pa[k][3] = f2tf(odd ? g3 : g2);
        }

        // ---- O += P @ V : Vt B-frags via ldmatrix ----
        const uint32_t vb = smb + bu*34816 + 17408 + foff;
        #pragma unroll
        for (int nv = 0; nv < 8; nv++) {
            #pragma unroll
            for (int kg = 0; kg < 4; kg++) {
                uint32_t b0, b1, b2, b3;
                ldsm4(b0, b1, b2, b3, vb + nv*2176 + kg*64);
                uint32_t bfa[2] = {b0, b1}, bfb[2] = {b2, b3};
                mma8(o[nv], pa[2*kg],   bfa);
                mma8(o[nv], pa[2*kg+1], bfb);
            }
        }
        __syncthreads();
    }

    // ---- epilogue (f2tf: outputs feed the next GEMM) ----
    float* obase = out + b*NSEQ*DIM + h*DH;
    #pragma unroll
    for (int h2 = 0; h2 < 2; h2++) {
        const float inv = STAGE1 ? 1.f : (1.f / lrow[h2]);
        const int n = qt*64 + warp*16 + lr + h2*8;
        #pragma unroll
        for (int nt = 0; nt < 8; nt++) {
            float2 v = make_float2(u2f(f2tf(o[nt][h2*2]*inv)),
                                   u2f(f2tf(o[nt][h2*2+1]*inv)));
            *(float2*)(obase + n*DIM + nt*8 + 2*lc) = v;
        }
    }
}

// ---------------- launch ----------------
extern "C" void kernel_launch(void* const* d_in, const int* in_sizes, int n_in,
                              void* d_out, int out_size)
{
    const float* x     = (const float*)d_in[0];
    const float* mask  = (const float*)d_in[1];
    const float* Wqkv1 = (const float*)d_in[2];
    const float* bqkv1 = (const float*)d_in[3];
    const float* Wqkv2 = (const float*)d_in[4];
    const float* bqkv2 = (const float*)d_in[5];
    const float* Wnn1  = (const float*)d_in[6];
    const float* bnn1  = (const float*)d_in[7];
    float* out = (float*)d_out;

    float *q1, *k1, *v1, *o1, *q2, *k2, *v2, *att, *xc, *w1, *w2, *wn;
    cudaGetSymbolAddress((void**)&q1, g_q1);
    cudaGetSymbolAddress((void**)&k1, g_k1);
    cudaGetSymbolAddress((void**)&v1, g_v1);
    cudaGetSymbolAddress((void**)&o1, g_o1);
    cudaGetSymbolAddress((void**)&q2, g_q2);
    cudaGetSymbolAddress((void**)&k2, g_k2);
    cudaGetSymbolAddress((void**)&v2, g_v2);
    cudaGetSymbolAddress((void**)&att, g_att);
    cudaGetSymbolAddress((void**)&xc, g_xc);
    cudaGetSymbolAddress((void**)&w1, g_w1);
    cudaGetSymbolAddress((void**)&w2, g_w2);
    cudaGetSymbolAddress((void**)&wn, g_wn);

    const int GSMEM = 73728, ASMEM = 69632;
    cudaFuncSetAttribute(gemm_tf32<1>, cudaFuncAttributeMaxDynamicSharedMemorySize, GSMEM);
    cudaFuncSetAttribute(gemm_tf32<0>, cudaFuncAttributeMaxDynamicSharedMemorySize, GSMEM);
    cudaFuncSetAttribute(attn_tf32<true>,  cudaFuncAttributeMaxDynamicSharedMemorySize, ASMEM);
    cudaFuncSetAttribute(attn_tf32<false>, cudaFuncAttributeMaxDynamicSharedMemorySize, ASMEM);

    const int M = BATCH * NSEQ;   // 8192

    // pre-pass: round x; round+transpose weights
    cvt_tf32<<<(M*DIM/4 + 255)/256, 256>>>((const float4*)x, (float4*)xc, M*DIM/4);
    transpose_w<<<dim3(3*DIM/32, DIM/32), dim3(32, 8)>>>(Wqkv1, w1, DIM, 3*DIM);
    transpose_w<<<dim3(3*DIM/32, DIM/32), dim3(32, 8)>>>(Wqkv2, w2, DIM, 3*DIM);
    transpose_w<<<dim3(DIM/32, DIM/32),   dim3(32, 8)>>>(Wnn1,  wn, DIM, DIM);

    dim3 gridQKV(3*DIM/128, M/128);   // 12 x 64
    dim3 gridOut(DIM/128, M/128);     // 4 x 64
    dim3 gridAtt(BH, NSEQ/64);        // 64 x 16

    gemm_tf32<1><<<gridQKV, 256, GSMEM>>>(xc, w1, bqkv1, nullptr, q1, k1, v1, 1.f);
    attn_tf32<true><<<gridAtt, 128, ASMEM>>>(q1, k1, v1, mask, o1);
    gemm_tf32<1><<<gridQKV, 256, GSMEM>>>(o1, w2, bqkv2, nullptr, q2, k2, v2, SCALE);
    attn_tf32<false><<<gridAtt, 128, ASMEM>>>(q2, k2, v2, nullptr, att);
    gemm_tf32<0><<<gridOut, 256, GSMEM>>>(att, wn, bnn1, out, nullptr, nullptr, nullptr, 1.f);
}

// round 6
// speedup vs baseline: 1.8183x; 1.8183x over previous
#include <cuda_runtime.h>
#include <cuda_fp16.h>
#include <cstdint>

#define BATCH 8
#define NSEQ  1024
#define DIM   512
#define NH    8
#define DH    64
#define BH    64
#define SCALE 0.044194173824159216f   // 512^-0.5

// ---------------- scratch (device globals: alloc-guard safe) ----------------
__device__ __half g_q1[BH*NSEQ*DH];
__device__ __half g_k1[BH*NSEQ*DH];
__device__ __half g_v1[BH*NSEQ*DH];
__device__ __half g_o1[BATCH*NSEQ*DIM];
__device__ __half g_q2[BH*NSEQ*DH];
__device__ __half g_k2[BH*NSEQ*DH];
__device__ __half g_v2[BH*NSEQ*DH];
__device__ __half g_att[BATCH*NSEQ*DIM];
__device__ __half g_xh[BATCH*NSEQ*DIM];
__device__ __half g_w1[DIM*3*DIM];     // fp16 W, original [K][N] layout
__device__ __half g_w2[DIM*3*DIM];
__device__ __half g_wn[DIM*DIM];

// ---------------- helpers ----------------
__device__ __forceinline__ uint32_t pkh2(float x, float y) {
    __half2 h = __floats2half2_rn(x, y);
    return *(uint32_t*)&h;
}
__device__ __forceinline__ void mma16(float* c, const uint32_t* a, const uint32_t* b) {
    asm volatile(
        "mma.sync.aligned.m16n8k16.row.col.f32.f16.f16.f32 "
        "{%0,%1,%2,%3}, {%4,%5,%6,%7}, {%8,%9}, {%0,%1,%2,%3};\n"
        : "+f"(c[0]), "+f"(c[1]), "+f"(c[2]), "+f"(c[3])
        : "r"(a[0]), "r"(a[1]), "r"(a[2]), "r"(a[3]), "r"(b[0]), "r"(b[1]));
}
__device__ __forceinline__ void ldsm4(uint32_t& r0, uint32_t& r1, uint32_t& r2, uint32_t& r3,
                                      uint32_t addr) {
    asm volatile("ldmatrix.sync.aligned.m8n8.x4.shared.b16 {%0,%1,%2,%3}, [%4];"
        : "=r"(r0), "=r"(r1), "=r"(r2), "=r"(r3) : "r"(addr));
}
__device__ __forceinline__ void ldsm4t(uint32_t& r0, uint32_t& r1, uint32_t& r2, uint32_t& r3,
                                       uint32_t addr) {
    asm volatile("ldmatrix.sync.aligned.m8n8.x4.trans.shared.b16 {%0,%1,%2,%3}, [%4];"
        : "=r"(r0), "=r"(r1), "=r"(r2), "=r"(r3) : "r"(addr));
}
__device__ __forceinline__ void cpa16(uint32_t dst, const void* src) {
    asm volatile("cp.async.cg.shared.global [%0], [%1], 16;" :: "r"(dst), "l"(src));
}
#define CP_COMMIT()  asm volatile("cp.async.commit_group;")
#define CP_WAIT(n)   asm volatile("cp.async.wait_group " #n ";")

// ---------------- pre-pass: f32 -> f16 ----------------
__global__ void cvt_h(const float4* __restrict__ src, uint4* __restrict__ dst, int n8) {
    int i = blockIdx.x * 256 + threadIdx.x;
    if (i < n8) {
        float4 a = src[2*i], b = src[2*i+1];
        uint4 o;
        o.x = pkh2(a.x, a.y); o.y = pkh2(a.z, a.w);
        o.z = pkh2(b.x, b.y); o.w = pkh2(b.z, b.w);
        dst[i] = o;
    }
}

// ---------------- GEMM: C[M,Nc] = A[M,512] @ W[512,Nc] + bias (fp16 mma) ----
// Block 128x128, 8 warps (warp 32x64), k-chunk 32, double-buffered cp.async.
// smem per buf: A 128 rows x 40 half (10240 B) + B 32 rows x 136 half (8704 B)
// = 18944 B. QKV=1: scatter cols into q/k/v [bh][n][d] half (coalesced half2).
template<int QKV>
__global__ __launch_bounds__(256) void gemm_h(
    const __half* __restrict__ A, const __half* __restrict__ W,
    const float* __restrict__ bias, float* __restrict__ C,
    __half* __restrict__ Qo, __half* __restrict__ Ko, __half* __restrict__ Vo,
    int Ncols, float qscale)
{
    extern __shared__ char smc[];
    const int tid = threadIdx.x, warp = tid >> 5, lane = tid & 31;
    const int wm = warp & 3, wn = warp >> 2, lr = lane >> 2, lc = lane & 3;
    const int row0 = blockIdx.y * 128, col0 = blockIdx.x * 128;
    const uint32_t smb = (uint32_t)__cvta_generic_to_shared(smc);

    float acc[2][8][4] = {};

    // prologue: k-tile 0 -> buf 0
    #pragma unroll
    for (int p = 0; p < 2; p++) {
        const int s = tid + 256*p;
        const int ra = s >> 2, ca = s & 3;          // A: 128 rows x 4 segs
        cpa16(smb + ra*80 + ca*16, A + (row0 + ra)*DIM + ca*8);
        const int rb = s >> 4, cb = s & 15;         // B: 32 rows x 16 segs
        cpa16(smb + 10240 + rb*272 + cb*16, W + rb*Ncols + col0 + cb*8);
    }
    CP_COMMIT();

    for (int i = 0; i < 16; i++) {
        const int bu = i & 1;
        if (i < 15) {
            const int nb = bu ^ 1, kt = (i+1)*32;
            #pragma unroll
            for (int p = 0; p < 2; p++) {
                const int s = tid + 256*p;
                const int ra = s >> 2, ca = s & 3;
                cpa16(smb + nb*18944 + ra*80 + ca*16,
                      A + (row0 + ra)*DIM + kt + ca*8);
                const int rb = s >> 4, cb = s & 15;
                cpa16(smb + nb*18944 + 10240 + rb*272 + cb*16,
                      W + (kt + rb)*Ncols + col0 + cb*8);
            }
            CP_COMMIT();
            CP_WAIT(1);
        } else {
            CP_WAIT(0);
        }
        __syncthreads();

        const uint32_t bufb = smb + bu*18944;
        #pragma unroll
        for (int kg = 0; kg < 2; kg++) {
            uint32_t af[2][4];
            #pragma unroll
            for (int mt = 0; mt < 2; mt++)
                ldsm4(af[mt][0], af[mt][1], af[mt][2], af[mt][3],
                      bufb + (wm*32 + mt*16 + (lane & 15))*80 + (lane>>4)*16 + kg*32);
            #pragma unroll
            for (int nb2 = 0; nb2 < 4; nb2++) {
                uint32_t r0, r1, r2, r3;
                ldsm4t(r0, r1, r2, r3,
                       bufb + 10240
                       + (kg*16 + ((lane>>3)&1)*8 + (lane&7))*272
                       + wn*128 + nb2*32 + (lane>>4)*16);
                uint32_t bf0[2] = {r0, r1}, bf1[2] = {r2, r3};
                mma16(acc[0][2*nb2],   af[0], bf0);
                mma16(acc[0][2*nb2+1], af[0], bf1);
                mma16(acc[1][2*nb2],   af[1], bf0);
                mma16(acc[1][2*nb2+1], af[1], bf1);
            }
        }
        __syncthreads();
    }

    // epilogue
    #pragma unroll
    for (int mt = 0; mt < 2; mt++) {
        const int rbase = row0 + wm*32 + mt*16 + lr;
        #pragma unroll
        for (int nt = 0; nt < 8; nt++) {
            const int cc = col0 + wn*64 + nt*8 + 2*lc;
            const float b0 = bias[cc], b1 = bias[cc+1];
            #pragma unroll
            for (int h2 = 0; h2 < 2; h2++) {
                const int r = rbase + h2*8;
                float v0 = acc[mt][nt][h2*2]   + b0;
                float v1 = acc[mt][nt][h2*2+1] + b1;
                if (QKV) {
                    const int part = cc >> 9;
                    const int hh   = (cc >> 6) & 7;
                    const int dd   = cc & 63;
                    const int bb   = r >> 10;
                    const int nn   = r & 1023;
                    const int bhh  = bb*NH + hh;
                    if (part == 0) { v0 *= qscale; v1 *= qscale; }
                    __half* dst = (part == 0) ? Qo : (part == 1) ? Ko : Vo;
                    *(uint32_t*)&dst[(bhh*NSEQ + nn)*DH + dd] = pkh2(v0, v1);
                } else {
                    *(float2*)&C[r*Ncols + cc] = make_float2(v0, v1);
                }
            }
        }
    }
}

// ---------------- flash attention (fp16 mma) ----------------
// Block: 128 queries, 8 warps (16 rows each), 64-key tiles, double-buffered.
// Q/K/V [bh][n][d] half (Q pre-scaled for stage 2). Output half.
// smem: buf b at b*18432: K 64x72 half (9216 B) then V 64x72 half (9216 B).
// Q staged in bytes [0,18432) (128 rows x 72 half) before the pipeline starts.
template<bool STAGE1>
__global__ __launch_bounds__(256) void attn_h(
    const __half* __restrict__ Q, const __half* __restrict__ K,
    const __half* __restrict__ V, const float* __restrict__ mask,
    __half* __restrict__ out)
{
    extern __shared__ char smc[];
    const int tid = threadIdx.x, warp = tid >> 5, lane = tid & 31;
    const int lr = lane >> 2, lc = lane & 3;
    const int bh = blockIdx.x, qt = blockIdx.y;
    const int b = bh >> 3, h = bh & 7;
    const uint32_t smb = (uint32_t)__cvta_generic_to_shared(smc);

    const __half* Qsrc = Q + (bh*NSEQ + qt*128)*DH;
    const __half* Ksrc = K + bh*NSEQ*DH;
    const __half* Vsrc = V + bh*NSEQ*DH;

    // ---- stage Q (128 rows x 8 segs), extract A-fragments ----
    #pragma unroll
    for (int p = 0; p < 4; p++) {
        const int s = tid + 256*p;
        const int row = s >> 3, c8 = s & 7;
        cpa16(smb + row*144 + c8*16, Qsrc + row*64 + c8*8);
    }
    CP_COMMIT();
    CP_WAIT(0);
    __syncthreads();

    uint32_t qf[4][4];
    #pragma unroll
    for (int kg = 0; kg < 4; kg++)
        ldsm4(qf[kg][0], qf[kg][1], qf[kg][2], qf[kg][3],
              smb + (warp*16 + (lane & 15))*144 + (lane>>4)*16 + kg*32);
    __syncthreads();

    // ---- prologue: tile 0 -> buf 0 ----
    #pragma unroll
    for (int p = 0; p < 2; p++) {
        const int s = tid + 256*p;
        const int row = s >> 3, c8 = s & 7;
        cpa16(smb + row*144 + c8*16,        Ksrc + row*64 + c8*8);
        cpa16(smb + 9216 + row*144 + c8*16, Vsrc + row*64 + c8*8);
    }
    CP_COMMIT();

    float o[8][4] = {};
    float mrow[2] = {-1e30f, -1e30f}, lrow[2] = {0.f, 0.f};

    for (int t = 0; t < 16; t++) {
        const int bu = t & 1;
        if (t < 15) {
            const int nb = bu ^ 1;
            #pragma unroll
            for (int p = 0; p < 2; p++) {
                const int s = tid + 256*p;
                const int row = s >> 3, c8 = s & 7;
                cpa16(smb + nb*18432 + row*144 + c8*16,
                      Ksrc + ((t+1)*64 + row)*64 + c8*8);
                cpa16(smb + nb*18432 + 9216 + row*144 + c8*16,
                      Vsrc + ((t+1)*64 + row)*64 + c8*8);
            }
            CP_COMMIT();
            CP_WAIT(1);
        } else {
            CP_WAIT(0);
        }
        __syncthreads();

        const uint32_t kbuf = smb + bu*18432;

        // ---- S = Q @ K^T : 16 ldsm + 32 mma per warp ----
        float s[8][4];
        #pragma unroll
        for (int nt = 0; nt < 8; nt++)
            #pragma unroll
            for (int u = 0; u < 4; u++) s[nt][u] = 0.f;
        #pragma unroll
        for (int kg = 0; kg < 4; kg++) {
            #pragma unroll
            for (int nt2 = 0; nt2 < 4; nt2++) {
                uint32_t r0, r1, r2, r3;
                ldsm4(r0, r1, r2, r3,
                      kbuf + (nt2*16 + ((lane>>4)&1)*8 + (lane&7))*144
                      + kg*32 + ((lane>>3)&1)*16);
                uint32_t bf0[2] = {r0, r1}, bf1[2] = {r2, r3};
                mma16(s[2*nt2],   qf[kg], bf0);
                mma16(s[2*nt2+1], qf[kg], bf1);
            }
        }

        // ---- elementwise ----
        if (STAGE1) {
            const int qrow0 = qt*128 + warp*16 + lr;
            #pragma unroll
            for (int nt = 0; nt < 8; nt++) {
                const int ccol = t*64 + nt*8 + 2*lc;
                float2 m0v = *(const float2*)(mask + qrow0*NSEQ + ccol);
                float2 m1v = *(const float2*)(mask + (qrow0+8)*NSEQ + ccol);
                s[nt][0] = 1.f / (1.f + __expf(-s[nt][0]*m0v.x));
                s[nt][1] = 1.f / (1.f + __expf(-s[nt][1]*m0v.y));
                s[nt][2] = 1.f / (1.f + __expf(-s[nt][2]*m1v.x));
                s[nt][3] = 1.f / (1.f + __expf(-s[nt][3]*m1v.y));
            }
        } else {
            #pragma unroll
            for (int h2 = 0; h2 < 2; h2++) {
                float tmax = -1e30f;
                #pragma unroll
                for (int nt = 0; nt < 8; nt++)
                    tmax = fmaxf(tmax, fmaxf(s[nt][h2*2], s[nt][h2*2+1]));
                tmax = fmaxf(tmax, __shfl_xor_sync(0xffffffffu, tmax, 1));
                tmax = fmaxf(tmax, __shfl_xor_sync(0xffffffffu, tmax, 2));
                const float mnew  = fmaxf(mrow[h2], tmax);
                const float alpha = __expf(mrow[h2] - mnew);
                mrow[h2] = mnew;
                float rsum = 0.f;
                #pragma unroll
                for (int nt = 0; nt < 8; nt++) {
                    const float p0 = __expf(s[nt][h2*2]   - mnew);
                    const float p1 = __expf(s[nt][h2*2+1] - mnew);
                    rsum += p0 + p1;
                    s[nt][h2*2]   = p0;
                    s[nt][h2*2+1] = p1;
                    o[nt][h2*2]   *= alpha;
                    o[nt][h2*2+1] *= alpha;
                }
                rsum += __shfl_xor_sync(0xffffffffu, rsum, 1);
                rsum += __shfl_xor_sync(0xffffffffu, rsum, 2);
                lrow[h2] = lrow[h2]*alpha + rsum;
            }
        }

        // ---- C-frag -> fp16 A-frag: pure register packing, no shuffles ----
        uint32_t pa[4][4];
        #pragma unroll
        for (int kt2 = 0; kt2 < 4; kt2++) {
            pa[kt2][0] = pkh2(s[2*kt2][0],   s[2*kt2][1]);
            pa[kt2][1] = pkh2(s[2*kt2][2],   s[2*kt2][3]);
            pa[kt2][2] = pkh2(s[2*kt2+1][0], s[2*kt2+1][1]);
            pa[kt2][3] = pkh2(s[2*kt2+1][2], s[2*kt2+1][3]);
        }

        // ---- O += P @ V : trans ldsm on row-major V ----
        const uint32_t vbuf = kbuf + 9216;
        #pragma unroll
        for (int kg = 0; kg < 4; kg++) {
            #pragma unroll
            for (int nb2 = 0; nb2 < 4; nb2++) {
                uint32_t r0, r1, r2, r3;
                ldsm4t(r0, r1, r2, r3,
                       vbuf + (kg*16 + ((lane>>3)&1)*8 + (lane&7))*144
                       + nb2*32 + (lane>>4)*16);
                uint32_t bf0[2] = {r0, r1}, bf1[2] = {r2, r3};
                mma16(o[2*nb2],   pa[kg], bf0);
                mma16(o[2*nb2+1], pa[kg], bf1);
            }
        }
        __syncthreads();
    }

    // ---- epilogue: half output (feeds next GEMM) ----
    __half* obase = out + b*NSEQ*DIM + h*DH;
    #pragma unroll
    for (int h2 = 0; h2 < 2; h2++) {
        const float inv = STAGE1 ? 1.f : (1.f / lrow[h2]);
        const int n = qt*128 + warp*16 + lr + h2*8;
        #pragma unroll
        for (int nt = 0; nt < 8; nt++)
            *(uint32_t*)&obase[n*DIM + nt*8 + 2*lc] =
                pkh2(o[nt][h2*2]*inv, o[nt][h2*2+1]*inv);
    }
}

// ---------------- launch ----------------
extern "C" void kernel_launch(void* const* d_in, const int* in_sizes, int n_in,
                              void* d_out, int out_size)
{
    const float* x     = (const float*)d_in[0];
    const float* mask  = (const float*)d_in[1];
    const float* Wqkv1 = (const float*)d_in[2];
    const float* bqkv1 = (const float*)d_in[3];
    const float* Wqkv2 = (const float*)d_in[4];
    const float* bqkv2 = (const float*)d_in[5];
    const float* Wnn1  = (const float*)d_in[6];
    const float* bnn1  = (const float*)d_in[7];
    float* out = (float*)d_out;

    __half *q1, *k1, *v1, *o1, *q2, *k2, *v2, *att, *xh, *w1, *w2, *wn;
    cudaGetSymbolAddress((void**)&q1, g_q1);
    cudaGetSymbolAddress((void**)&k1, g_k1);
    cudaGetSymbolAddress((void**)&v1, g_v1);
    cudaGetSymbolAddress((void**)&o1, g_o1);
    cudaGetSymbolAddress((void**)&q2, g_q2);
    cudaGetSymbolAddress((void**)&k2, g_k2);
    cudaGetSymbolAddress((void**)&v2, g_v2);
    cudaGetSymbolAddress((void**)&att, g_att);
    cudaGetSymbolAddress((void**)&xh, g_xh);
    cudaGetSymbolAddress((void**)&w1, g_w1);
    cudaGetSymbolAddress((void**)&w2, g_w2);
    cudaGetSymbolAddress((void**)&wn, g_wn);

    const int GSMEM = 37888, ASMEM = 36864;
    cudaFuncSetAttribute(gemm_h<1>, cudaFuncAttributeMaxDynamicSharedMemorySize, GSMEM);
    cudaFuncSetAttribute(gemm_h<0>, cudaFuncAttributeMaxDynamicSharedMemorySize, GSMEM);
    cudaFuncSetAttribute(attn_h<true>,  cudaFuncAttributeMaxDynamicSharedMemorySize, ASMEM);
    cudaFuncSetAttribute(attn_h<false>, cudaFuncAttributeMaxDynamicSharedMemorySize, ASMEM);

    const int M = BATCH * NSEQ;   // 8192

    // pre-pass: f32 -> f16 (x and all weights; layouts unchanged)
    cvt_h<<<(M*DIM/8 + 255)/256, 256>>>((const float4*)x, (uint4*)xh, M*DIM/8);
    cvt_h<<<(DIM*3*DIM/8 + 255)/256, 256>>>((const float4*)Wqkv1, (uint4*)w1, DIM*3*DIM/8);
    cvt_h<<<(DIM*3*DIM/8 + 255)/256, 256>>>((const float4*)Wqkv2, (uint4*)w2, DIM*3*DIM/8);
    cvt_h<<<(DIM*DIM/8 + 255)/256, 256>>>((const float4*)Wnn1, (uint4*)wn, DIM*DIM/8);

    dim3 gridQKV(3*DIM/128, M/128);   // 12 x 64
    dim3 gridOut(DIM/128, M/128);     // 4 x 64
    dim3 gridAtt(BH, NSEQ/128);       // 64 x 8

    gemm_h<1><<<gridQKV, 256, GSMEM>>>(xh, w1, bqkv1, nullptr, q1, k1, v1, 3*DIM, 1.f);
    attn_h<true><<<gridAtt, 256, ASMEM>>>(q1, k1, v1, mask, o1);
    gemm_h<1><<<gridQKV, 256, GSMEM>>>(o1, w2, bqkv2, nullptr, q2, k2, v2, 3*DIM, SCALE);
    attn_h<false><<<gridAtt, 256, ASMEM>>>(q2, k2, v2, nullptr, att);
    gemm_h<0><<<gridOut, 256, GSMEM>>>(att, wn, bnn1, out, nullptr, nullptr, nullptr, DIM, 1.f);
}